// round 1
// baseline (speedup 1.0000x reference)
#include <cuda_runtime.h>
#include <math.h>

#define NROWS 16384
#define DIM   64
#define FULLMASK 0xffffffffu

// Scratch: t1[i][c] = (logmap0(x) @ W^T)[i][c+1], c = 0..62; column 63 = 0 pad.
__device__ float g_t1[NROWS * DIM];

// ---------------------------------------------------------------------------
// Kernel A: t1 = s_i * (x[i,1:] @ W[1:,1:]^T), with s_i = acosh(theta)/yn.
// grid 512 blocks x 256 threads; each block computes 32 rows (4 at a time).
// ---------------------------------------------------------------------------
__global__ void __launch_bounds__(256) compute_t1_kernel(
    const float* __restrict__ x, const float* __restrict__ W)
{
    __shared__ float Ws[DIM * 65];   // padded stride 65: conflict-free column reads
    __shared__ float xs[4][DIM];

    int tid = threadIdx.x;
    for (int idx = tid; idx < DIM * DIM; idx += 256) {
        int r = idx >> 6, c = idx & 63;
        Ws[r * 65 + c] = W[idx];
    }
    __syncthreads();

    int sub = tid >> 6;      // row-in-quad 0..3
    int j   = tid & 63;      // output column 0..63
    int row0 = blockIdx.x * 32;

    for (int rr = 0; rr < 32; rr += 4) {
        int i = row0 + rr + sub;
        xs[sub][j] = x[(size_t)i * DIM + j];
        __syncthreads();

        // norm of tail (redundant per thread; cheap)
        float nn = 0.f;
        #pragma unroll
        for (int d = 1; d < DIM; d++) { float v = xs[sub][d]; nn += v * v; }
        float yn    = fmaxf(sqrtf(nn), 1e-15f);
        float theta = fmaxf(xs[sub][0], 1.0f + 1e-7f);
        float s     = acoshf(theta) / yn;

        float outv = 0.f;
        if (j < 63) {
            float acc = 0.f;
            #pragma unroll
            for (int d = 1; d < DIM; d++)
                acc += xs[sub][d] * Ws[(j + 1) * 65 + d];
            outv = s * acc;
        }
        g_t1[(size_t)i * DIM + j] = outv;
        __syncthreads();
    }
}

// ---------------------------------------------------------------------------
// Kernel B: one warp per output row.
//   m = adj[row] @ t1 (sparse scan: adj entries are 0 or 1/deg, all >= 0)
//   out[row] = proj(expmap0(relu(m)))
// adj is streamed once (1.07 GB) -> DRAM-bound. t1 gathers hit L2 (4 MB).
// ---------------------------------------------------------------------------
__global__ void __launch_bounds__(256) spmm_epilogue_kernel(
    const float* __restrict__ adj, float* __restrict__ out)
{
    const int warp = threadIdx.x >> 5;
    const int lane = threadIdx.x & 31;
    const int row  = blockIdx.x * 8 + warp;

    const float4* __restrict__ a4 =
        reinterpret_cast<const float4*>(adj) + (size_t)row * (NROWS / 4);
    const float* __restrict__ t1 = g_t1;

    float acc0 = 0.f;   // m[lane]
    float acc1 = 0.f;   // m[lane+32] (lane 31 -> pad col 63, always 0)

    // 4096 float4 per row / 32 lanes = 128 lane-iterations; unroll 8 for MLP.
    #pragma unroll 1
    for (int it = 0; it < 128; it += 8) {
        float4 v[8];
        #pragma unroll
        for (int u = 0; u < 8; u++)
            v[u] = __ldcs(&a4[(it + u) * 32 + lane]);

        #pragma unroll
        for (int u = 0; u < 8; u++) {
            // entries are >= 0, so sum > 0 <=> any nonzero (no cancellation)
            float s = (v[u].x + v[u].y) + (v[u].z + v[u].w);
            unsigned m = __ballot_sync(FULLMASK, s > 0.f);
            while (m) {
                int b = __ffs(m) - 1;
                m &= m - 1;
                float hx = __shfl_sync(FULLMASK, v[u].x, b);
                float hy = __shfl_sync(FULLMASK, v[u].y, b);
                float hz = __shfl_sync(FULLMASK, v[u].z, b);
                float hw = __shfl_sync(FULLMASK, v[u].w, b);
                int jb = ((it + u) * 32 + b) * 4;
                if (hx != 0.f) {
                    const float* tr = t1 + (size_t)(jb + 0) * DIM;
                    acc0 += hx * tr[lane]; acc1 += hx * tr[lane + 32];
                }
                if (hy != 0.f) {
                    const float* tr = t1 + (size_t)(jb + 1) * DIM;
                    acc0 += hy * tr[lane]; acc1 += hy * tr[lane + 32];
                }
                if (hz != 0.f) {
                    const float* tr = t1 + (size_t)(jb + 2) * DIM;
                    acc0 += hz * tr[lane]; acc1 += hz * tr[lane + 32];
                }
                if (hw != 0.f) {
                    const float* tr = t1 + (size_t)(jb + 3) * DIM;
                    acc0 += hw * tr[lane]; acc1 += hw * tr[lane + 32];
                }
            }
        }
    }

    // Epilogue: r = relu(m); out = [sqrt(1+sinh^2(rn)), sinh(rn)*r/rn]
    float r0 = fmaxf(acc0, 0.f);
    float r1 = fmaxf(acc1, 0.f);
    float nn = r0 * r0 + r1 * r1;
    #pragma unroll
    for (int o = 16; o; o >>= 1)
        nn += __shfl_xor_sync(FULLMASK, nn, o);

    float rn    = sqrtf(nn);
    float xn    = fmaxf(rn, 1e-15f);
    float sh    = sinhf(xn);
    float scale = sh / xn;
    float first = sqrtf(fmaxf(1.0f + sh * sh, 1e-15f));

    float* o = out + (size_t)row * DIM;
    if (lane == 0) o[0] = first;
    o[1 + lane] = scale * r0;
    if (lane < 31) o[33 + lane] = scale * r1;
}

// ---------------------------------------------------------------------------
extern "C" void kernel_launch(void* const* d_in, const int* in_sizes, int n_in,
                              void* d_out, int out_size)
{
    // Identify inputs by element count (robust to ordering).
    const float *x = nullptr, *adj = nullptr, *W = nullptr;
    for (int k = 0; k < n_in; k++) {
        long long n = in_sizes[k];
        if (n == (long long)NROWS * NROWS)      adj = (const float*)d_in[k];
        else if (n == (long long)DIM * DIM)     W   = (const float*)d_in[k];
        else if (n == (long long)NROWS * DIM)   x   = (const float*)d_in[k];
    }
    float* out = (float*)d_out;

    compute_t1_kernel<<<512, 256>>>(x, W);
    spmm_epilogue_kernel<<<NROWS / 8, 256>>>(adj, out);
}